// round 4
// baseline (speedup 1.0000x reference)
#include <cuda_runtime.h>
#include <math.h>
#include <stdint.h>

#define TB 2048
#define CB 1024
#define BSZ 2
#define HH 16
#define DD 64
#define NCH 32   // chunks of 64 along T
#define BHN 32   // BSZ*HH

// ---------------- scratch (static device allocations; no cudaMalloc) ----------
__device__ float g_qkv[(size_t)BSZ * TB * 3 * CB];        // 50.3 MB
__device__ float g_kv [(size_t)BHN * NCH * DD * DD];      // 16.8 MB
__device__ float g_kz [(size_t)BHN * NCH * DD];
__device__ float g_y  [(size_t)BSZ * TB * CB];            // 16.8 MB

__device__ __forceinline__ float phi(float x) {           // elu(x)+1
    return x > 0.f ? x + 1.f : expf(x);
}

__device__ __forceinline__ uint32_t f2tf32(float x) {
    uint32_t r;
    asm("cvt.rna.tf32.f32 %0, %1;" : "=r"(r) : "f"(x));
    return r;
}

__device__ __forceinline__ void cp_async16(void* sptr, const void* gptr) {
    uint32_t sa = (uint32_t)__cvta_generic_to_shared(sptr);
    asm volatile("cp.async.cg.shared.global [%0], [%1], 16;" :: "r"(sa), "l"(gptr));
}

// ---------------- TF32 tensor-core GEMM, 3-stage cp.async pipeline -------------
// C(MxN) = A(MxK=1024) @ B(1024xN). 128x128 block tile, 256 threads (8 warps,
// 2x4), warp tile 64x32, K-step 32, mma.sync.m16n8k8.tf32.
// Smem strides: A pad 36 -> bank (4r+c)%32 conflict-free on fragment load;
// B pad 136 -> bank (8k+n)%32 conflict-free.
#define AS_W 4608            // 128*36 words per stage
#define BS_W 4352            // 32*136 words per stage
#define GEMM_SMEM_BYTES (3 * (AS_W + BS_W) * 4)   // 107520

template <int N>
__device__ __forceinline__ void tgemm_body(const float* __restrict__ A,
                                           const float* __restrict__ B,
                                           float* __restrict__ C) {
    extern __shared__ float smem[];
    float* sA = smem;                 // 3 stages of [128][36]
    float* sB = smem + 3 * AS_W;      // 3 stages of [32][136]

    const int K = 1024;
    const int NITER = 32;

    int tid  = threadIdx.x;
    int lane = tid & 31;
    int warp = tid >> 5;
    int wm = (warp >> 2) * 64;        // 0 / 64
    int wn = (warp & 3) * 32;         // 0,32,64,96
    int bm = blockIdx.y * 128;
    int bn = blockIdx.x * 128;

    int ar = tid >> 3, ac = (tid & 7) << 2;   // A loader: 128 rows x 32 cols
    int br = tid >> 5, bc = (tid & 31) << 2;  // B loader: 32 rows x 128 cols
    const int lq = lane >> 2;
    const int lr = lane & 3;

    float acc[4][4][4];
#pragma unroll
    for (int mi = 0; mi < 4; mi++)
#pragma unroll
        for (int ni = 0; ni < 4; ni++)
#pragma unroll
            for (int r = 0; r < 4; r++) acc[mi][ni][r] = 0.f;

    // ---- prefetch helper (tile t -> stage s) ----
    auto prefetch = [&](int t, int s) {
        int k0 = t * 32;
        float* As_ = sA + s * AS_W;
        float* Bs_ = sB + s * BS_W;
#pragma unroll
        for (int i = 0; i < 4; i++) {
            int rr = ar + i * 32;
            cp_async16(&As_[rr * 36 + ac],
                       A + (size_t)(bm + rr) * K + k0 + ac);
        }
#pragma unroll
        for (int i = 0; i < 4; i++) {
            int rr = br + i * 8;
            cp_async16(&Bs_[rr * 136 + bc],
                       B + (size_t)(k0 + rr) * N + bn + bc);
        }
        asm volatile("cp.async.commit_group;" ::: "memory");
    };

    prefetch(0, 0);
    prefetch(1, 1);

    for (int it = 0; it < NITER; it++) {
        if (it < NITER - 2)
            asm volatile("cp.async.wait_group 1;" ::: "memory");
        else
            asm volatile("cp.async.wait_group 0;" ::: "memory");
        __syncthreads();

        if (it + 2 < NITER) prefetch(it + 2, (it + 2) % 3);

        const float* As_ = sA + (it % 3) * AS_W;
        const float* Bs_ = sB + (it % 3) * BS_W;

#pragma unroll
        for (int ks = 0; ks < 4; ks++) {
            int kb = ks * 8;
            uint32_t af[4][4], bf[4][2];
#pragma unroll
            for (int mi = 0; mi < 4; mi++) {
                int r0 = wm + mi * 16 + lq;
                af[mi][0] = f2tf32(As_[(r0    ) * 36 + kb + lr]);
                af[mi][1] = f2tf32(As_[(r0 + 8) * 36 + kb + lr]);
                af[mi][2] = f2tf32(As_[(r0    ) * 36 + kb + 4 + lr]);
                af[mi][3] = f2tf32(As_[(r0 + 8) * 36 + kb + 4 + lr]);
            }
#pragma unroll
            for (int ni = 0; ni < 4; ni++) {
                int c0 = wn + ni * 8 + lq;
                bf[ni][0] = f2tf32(Bs_[(kb + lr    ) * 136 + c0]);
                bf[ni][1] = f2tf32(Bs_[(kb + 4 + lr) * 136 + c0]);
            }
#pragma unroll
            for (int mi = 0; mi < 4; mi++)
#pragma unroll
                for (int ni = 0; ni < 4; ni++) {
                    asm volatile(
                        "mma.sync.aligned.m16n8k8.row.col.f32.tf32.tf32.f32 "
                        "{%0,%1,%2,%3}, {%4,%5,%6,%7}, {%8,%9}, {%0,%1,%2,%3};"
                        : "+f"(acc[mi][ni][0]), "+f"(acc[mi][ni][1]),
                          "+f"(acc[mi][ni][2]), "+f"(acc[mi][ni][3])
                        : "r"(af[mi][0]), "r"(af[mi][1]), "r"(af[mi][2]), "r"(af[mi][3]),
                          "r"(bf[ni][0]), "r"(bf[ni][1]));
                }
        }
    }

#pragma unroll
    for (int mi = 0; mi < 4; mi++)
#pragma unroll
        for (int ni = 0; ni < 4; ni++) {
            int r = bm + wm + mi * 16 + lq;
            int c = bn + wn + ni * 8 + lr * 2;
            *(float2*)(C + (size_t)r * N + c) =
                make_float2(acc[mi][ni][0], acc[mi][ni][1]);
            *(float2*)(C + (size_t)(r + 8) * N + c) =
                make_float2(acc[mi][ni][2], acc[mi][ni][3]);
        }
}

__global__ __launch_bounds__(256) void gemm_qkv_kernel(const float* __restrict__ x,
                                                       const float* __restrict__ w) {
    tgemm_body<3 * CB>(x, w, g_qkv);
}
__global__ __launch_bounds__(256) void gemm_proj_kernel(const float* __restrict__ w,
                                                        float* __restrict__ out) {
    tgemm_body<CB>(g_y, w, out);
}

// ---------------- Phase A: per-chunk KV = phi(K)^T V  and  kz = sum phi(k) ----
__global__ __launch_bounds__(256) void chunk_kv_kernel() {
    int bid = blockIdx.x;
    int bh = bid >> 5, c = bid & 31;
    int b = bh >> 4, h = bh & 15;
    int tid = threadIdx.x;
    __shared__ float sK[64][65];
    __shared__ float sV[64][65];

    const float* base = g_qkv + (size_t)(b * TB + c * 64) * (3 * CB) + h * 64;
#pragma unroll
    for (int it = 0; it < 4; it++) {
        int idx = tid + it * 256;            // 0..1023
        int r = idx >> 4;
        int c4 = (idx & 15) << 2;
        float4 kk = *(const float4*)(base + (size_t)r * (3 * CB) + CB + c4);
        float4 vv = *(const float4*)(base + (size_t)r * (3 * CB) + 2 * CB + c4);
        sK[r][c4 + 0] = phi(kk.x); sK[r][c4 + 1] = phi(kk.y);
        sK[r][c4 + 2] = phi(kk.z); sK[r][c4 + 3] = phi(kk.w);
        sV[r][c4 + 0] = vv.x; sV[r][c4 + 1] = vv.y;
        sV[r][c4 + 2] = vv.z; sV[r][c4 + 3] = vv.w;
    }
    __syncthreads();

    int ii0 = (tid >> 4) << 2;
    int jj0 = (tid & 15) << 2;
    float a[4][4];
#pragma unroll
    for (int i = 0; i < 4; i++)
#pragma unroll
        for (int j = 0; j < 4; j++) a[i][j] = 0.f;

#pragma unroll 4
    for (int t = 0; t < 64; t++) {
        float kr[4], vr[4];
#pragma unroll
        for (int i = 0; i < 4; i++) kr[i] = sK[t][ii0 + i];
#pragma unroll
        for (int j = 0; j < 4; j++) vr[j] = sV[t][jj0 + j];
#pragma unroll
        for (int i = 0; i < 4; i++)
#pragma unroll
            for (int j = 0; j < 4; j++)
                a[i][j] += kr[i] * vr[j];
    }

    float* kvout = g_kv + (size_t)(bh * NCH + c) * (DD * DD);
#pragma unroll
    for (int i = 0; i < 4; i++)
        *(float4*)&kvout[(ii0 + i) * 64 + jj0] =
            make_float4(a[i][0], a[i][1], a[i][2], a[i][3]);

    if (tid < 64) {
        float s = 0.f;
#pragma unroll 8
        for (int t = 0; t < 64; t++) s += sK[t][tid];
        g_kz[(size_t)(bh * NCH + c) * 64 + tid] = s;
    }
}

// ---------------- Phase B: exclusive prefix over chunks (kv + kz merged) ------
__global__ void scan_all_kernel() {
    int e = blockIdx.x * 256 + threadIdx.x;
    if (e < BHN * 4096) {                       // kv part: 131072 lanes
        int bh = e >> 12, ij = e & 4095;
        float* p = g_kv + (size_t)bh * NCH * 4096 + ij;
        float run = 0.f;
#pragma unroll 4
        for (int c = 0; c < NCH; c++) {
            float v = p[(size_t)c * 4096];
            p[(size_t)c * 4096] = run;
            run += v;
        }
    } else if (e < BHN * 4096 + BHN * 64) {     // kz part: 2048 lanes
        int e2 = e - BHN * 4096;
        int bh = e2 >> 6, i = e2 & 63;
        float* p = g_kz + (size_t)bh * NCH * 64 + i;
        float run = 0.f;
#pragma unroll 4
        for (int c = 0; c < NCH; c++) {
            float v = p[(size_t)c * 64];
            p[(size_t)c * 64] = run;
            run += v;
        }
    }
}

// ---------------- Phase C: per-chunk output ----------------------------------
__global__ __launch_bounds__(256) void attn_out_kernel() {
    int bid = blockIdx.x;
    int bh = bid >> 5, cidx = bid & 31;
    int b = bh >> 4, h = bh & 15;
    int tid = threadIdx.x;
    int t = tid >> 2;          // row 0..63
    int cc = tid & 3;          // column-group

    __shared__ float sQ[64][65];
    __shared__ float sK[64][65];
    __shared__ float sS[16][64];
    __shared__ float sV[16][64];
    __shared__ float sA[64][17];
    __shared__ float sz[64];

    const float* base = g_qkv + (size_t)(b * TB + cidx * 64) * (3 * CB) + h * 64;
#pragma unroll
    for (int it = 0; it < 4; it++) {
        int idx = tid + it * 256;
        int r = idx >> 4;
        int c4 = (idx & 15) << 2;
        float4 q4 = *(const float4*)(base + (size_t)r * (3 * CB) + c4);
        float4 k4 = *(const float4*)(base + (size_t)r * (3 * CB) + CB + c4);
        sQ[r][c4 + 0] = phi(q4.x); sQ[r][c4 + 1] = phi(q4.y);
        sQ[r][c4 + 2] = phi(q4.z); sQ[r][c4 + 3] = phi(q4.w);
        sK[r][c4 + 0] = phi(k4.x); sK[r][c4 + 1] = phi(k4.y);
        sK[r][c4 + 2] = phi(k4.z); sK[r][c4 + 3] = phi(k4.w);
    }
    if (tid < 64) sz[tid] = g_kz[(size_t)(bh * NCH + cidx) * 64 + tid];
    __syncthreads();

    float acc[16];
#pragma unroll
    for (int dd = 0; dd < 16; dd++) acc[dd] = 0.f;
    float den = 0.f;
#pragma unroll 8
    for (int i = 0; i < 64; i++) den += sQ[t][i] * sz[i];

    // inter-chunk: Q @ S  (S streamed in 16-row slices)
    const float* Sg = g_kv + (size_t)(bh * NCH + cidx) * 4096;
    for (int i0 = 0; i0 < 64; i0 += 16) {
        {
            int r = tid >> 4, c4 = (tid & 15) << 2;
            *(float4*)&sS[r][c4] = *(const float4*)&Sg[(i0 + r) * 64 + c4];
        }
        __syncthreads();
#pragma unroll
        for (int i = 0; i < 16; i++) {
            float qv = sQ[t][i0 + i];
#pragma unroll
            for (int dd = 0; dd < 16; dd++)
                acc[dd] += qv * sS[i][cc + 4 * dd];
        }
        __syncthreads();
    }

    // intra-chunk: masked QK^T, then @V, V streamed in 16-row slices
    for (int s0 = 0; s0 < 64; s0 += 16) {
        {
            int r = tid >> 4, c4 = (tid & 15) << 2;
            *(float4*)&sV[r][c4] =
                *(const float4*)(base + (size_t)(s0 + r) * (3 * CB) + 2 * CB + c4);
        }
#pragma unroll
        for (int u = 0; u < 4; u++) {
            int ss = cc * 4 + u;
            int s = s0 + ss;
            float a = 0.f;
            if (s <= t) {
#pragma unroll 8
                for (int i = 0; i < 64; i++) a += sQ[t][i] * sK[s][i];
            }
            sA[t][ss] = a;
        }
        __syncthreads();
#pragma unroll
        for (int ss = 0; ss < 16; ss++) {
            float a = sA[t][ss];
            den += a;
#pragma unroll
            for (int dd = 0; dd < 16; dd++)
                acc[dd] += a * sV[ss][cc + 4 * dd];
        }
        __syncthreads();
    }

    float inv = 1.f / (den + 1e-6f);
    float* yout = g_y + (size_t)(b * TB + cidx * 64 + t) * CB + h * 64;
#pragma unroll
    for (int dd = 0; dd < 16; dd++)
        yout[cc + 4 * dd] = acc[dd] * inv;
}

// ---------------- launch ------------------------------------------------------
extern "C" void kernel_launch(void* const* d_in, const int* in_sizes, int n_in,
                              void* d_out, int out_size) {
    const float* x      = (const float*)d_in[0];
    const float* w_attn = (const float*)d_in[1];
    const float* w_proj = (const float*)d_in[2];
    float* out = (float*)d_out;

    cudaFuncSetAttribute(gemm_qkv_kernel,
                         cudaFuncAttributeMaxDynamicSharedMemorySize, GEMM_SMEM_BYTES);
    cudaFuncSetAttribute(gemm_proj_kernel,
                         cudaFuncAttributeMaxDynamicSharedMemorySize, GEMM_SMEM_BYTES);

    dim3 g1(3 * CB / 128, BSZ * TB / 128);   // (24, 32)
    gemm_qkv_kernel<<<g1, 256, GEMM_SMEM_BYTES>>>(x, w_attn);

    chunk_kv_kernel<<<BHN * NCH, 256>>>();
    scan_all_kernel<<<(BHN * 4096 + BHN * 64 + 255) / 256, 256>>>();
    attn_out_kernel<<<BHN * NCH, 256>>>();

    dim3 g2(CB / 128, BSZ * TB / 128);       // (8, 32)
    gemm_proj_kernel<<<g2, 256, GEMM_SMEM_BYTES>>>(w_proj, out);
}

// round 5
// speedup vs baseline: 1.3467x; 1.3467x over previous
#include <cuda_runtime.h>
#include <math.h>
#include <stdint.h>

#define TB 2048
#define CB 1024
#define BSZ 2
#define HH 16
#define DD 64
#define NCH 32   // chunks of 64 along T
#define BHN 32   // BSZ*HH

// ---------------- scratch (static device allocations; no cudaMalloc) ----------
__device__ float g_qkv[(size_t)BSZ * TB * 3 * CB];        // 50.3 MB
__device__ float g_kv [(size_t)BHN * NCH * DD * DD];      // 16.8 MB
__device__ float g_kz [(size_t)BHN * NCH * DD];
__device__ float g_y  [(size_t)BSZ * TB * CB];            // 16.8 MB

__device__ __forceinline__ float phi(float x) {           // elu(x)+1
    return x > 0.f ? x + 1.f : expf(x);
}

__device__ __forceinline__ uint32_t f2tf32(float x) {
    uint32_t r;
    asm("cvt.rna.tf32.f32 %0, %1;" : "=r"(r) : "f"(x));
    return r;
}

#define MMA_TF32(C, A0, A1, A2, A3, B0, B1)                                     \
    asm volatile(                                                               \
        "mma.sync.aligned.m16n8k8.row.col.f32.tf32.tf32.f32 "                   \
        "{%0,%1,%2,%3}, {%4,%5,%6,%7}, {%8,%9}, {%0,%1,%2,%3};"                 \
        : "+f"((C)[0]), "+f"((C)[1]), "+f"((C)[2]), "+f"((C)[3])                \
        : "r"(A0), "r"(A1), "r"(A2), "r"(A3), "r"(B0), "r"(B1))

// ---------------- TF32 tensor-core GEMM (R3 winner, single-buffer) -------------
// C(MxN)=A(MxK)@B(KxN), 128x128 block, 8 warps (2x4), warp tile 64x32, K-step 32.
__device__ __forceinline__ void tgemm_body(const float* __restrict__ A,
                                           const float* __restrict__ B,
                                           float* __restrict__ C,
                                           int N, int K) {
    __shared__ uint32_t As[128][36];   // bank = (4*row+col)%32 -> conflict free
    __shared__ uint32_t Bs[32][136];   // bank = (8*k+n)%32   -> conflict free

    int tid  = threadIdx.x;
    int lane = tid & 31;
    int warp = tid >> 5;
    int wm = (warp >> 2) * 64;         // 0 / 64
    int wn = (warp & 3) * 32;          // 0,32,64,96
    int bm = blockIdx.y * 128;
    int bn = blockIdx.x * 128;

    float acc[4][4][4];
#pragma unroll
    for (int mi = 0; mi < 4; mi++)
#pragma unroll
        for (int ni = 0; ni < 4; ni++)
#pragma unroll
            for (int r = 0; r < 4; r++) acc[mi][ni][r] = 0.f;

    int ar = tid >> 3, ac = (tid & 7) << 2;
    int br = tid >> 5, bc = (tid & 31) << 2;
    const int lq = lane >> 2;
    const int lr = lane & 3;

    for (int k0 = 0; k0 < K; k0 += 32) {
        float4 a[4], b[4];
#pragma unroll
        for (int i = 0; i < 4; i++) {
            int rr = ar + i * 32;
            a[i] = *(const float4*)(A + (size_t)(bm + rr) * K + k0 + ac);
        }
#pragma unroll
        for (int i = 0; i < 4; i++) {
            int rr = br + i * 8;
            b[i] = *(const float4*)(B + (size_t)(k0 + rr) * N + bn + bc);
        }
        __syncthreads();
#pragma unroll
        for (int i = 0; i < 4; i++) {
            int rr = ar + i * 32;
            As[rr][ac + 0] = f2tf32(a[i].x); As[rr][ac + 1] = f2tf32(a[i].y);
            As[rr][ac + 2] = f2tf32(a[i].z); As[rr][ac + 3] = f2tf32(a[i].w);
        }
#pragma unroll
        for (int i = 0; i < 4; i++) {
            int rr = br + i * 8;
            Bs[rr][bc + 0] = f2tf32(b[i].x); Bs[rr][bc + 1] = f2tf32(b[i].y);
            Bs[rr][bc + 2] = f2tf32(b[i].z); Bs[rr][bc + 3] = f2tf32(b[i].w);
        }
        __syncthreads();

#pragma unroll
        for (int ks = 0; ks < 4; ks++) {
            int kb = ks * 8;
            uint32_t af[4][4], bf[4][2];
#pragma unroll
            for (int mi = 0; mi < 4; mi++) {
                int r0 = wm + mi * 16 + lq;
                af[mi][0] = As[r0    ][kb + lr];
                af[mi][1] = As[r0 + 8][kb + lr];
                af[mi][2] = As[r0    ][kb + 4 + lr];
                af[mi][3] = As[r0 + 8][kb + 4 + lr];
            }
#pragma unroll
            for (int ni = 0; ni < 4; ni++) {
                int c0 = wn + ni * 8 + lq;
                bf[ni][0] = Bs[kb + lr    ][c0];
                bf[ni][1] = Bs[kb + 4 + lr][c0];
            }
#pragma unroll
            for (int mi = 0; mi < 4; mi++)
#pragma unroll
                for (int ni = 0; ni < 4; ni++)
                    MMA_TF32(acc[mi][ni], af[mi][0], af[mi][1], af[mi][2], af[mi][3],
                             bf[ni][0], bf[ni][1]);
        }
    }

#pragma unroll
    for (int mi = 0; mi < 4; mi++)
#pragma unroll
        for (int ni = 0; ni < 4; ni++) {
            int r = bm + wm + mi * 16 + lq;
            int c = bn + wn + ni * 8 + lr * 2;
            *(float2*)(C + (size_t)r * N + c) =
                make_float2(acc[mi][ni][0], acc[mi][ni][1]);
            *(float2*)(C + (size_t)(r + 8) * N + c) =
                make_float2(acc[mi][ni][2], acc[mi][ni][3]);
        }
}

__global__ __launch_bounds__(256) void gemm_qkv_kernel(const float* __restrict__ x,
                                                       const float* __restrict__ w) {
    tgemm_body(x, w, g_qkv, 3 * CB, CB);
}
__global__ __launch_bounds__(256) void gemm_proj_kernel(const float* __restrict__ w,
                                                        float* __restrict__ out) {
    tgemm_body(g_y, w, out, CB, CB);
}

// ---------------- Phase A: per-chunk KV = phi(K)^T V  and  kz = sum phi(k) ----
__global__ __launch_bounds__(256) void chunk_kv_kernel() {
    int bid = blockIdx.x;
    int bh = bid >> 5, c = bid & 31;
    int b = bh >> 4, h = bh & 15;
    int tid = threadIdx.x;
    __shared__ float sK[64][65];
    __shared__ float sV[64][65];

    const float* base = g_qkv + (size_t)(b * TB + c * 64) * (3 * CB) + h * 64;
#pragma unroll
    for (int it = 0; it < 4; it++) {
        int idx = tid + it * 256;            // 0..1023
        int r = idx >> 4;
        int c4 = (idx & 15) << 2;
        float4 kk = *(const float4*)(base + (size_t)r * (3 * CB) + CB + c4);
        float4 vv = *(const float4*)(base + (size_t)r * (3 * CB) + 2 * CB + c4);
        sK[r][c4 + 0] = phi(kk.x); sK[r][c4 + 1] = phi(kk.y);
        sK[r][c4 + 2] = phi(kk.z); sK[r][c4 + 3] = phi(kk.w);
        sV[r][c4 + 0] = vv.x; sV[r][c4 + 1] = vv.y;
        sV[r][c4 + 2] = vv.z; sV[r][c4 + 3] = vv.w;
    }
    __syncthreads();

    int ii0 = (tid >> 4) << 2;
    int jj0 = (tid & 15) << 2;
    float a[4][4];
#pragma unroll
    for (int i = 0; i < 4; i++)
#pragma unroll
        for (int j = 0; j < 4; j++) a[i][j] = 0.f;

#pragma unroll 4
    for (int t = 0; t < 64; t++) {
        float kr[4], vr[4];
#pragma unroll
        for (int i = 0; i < 4; i++) kr[i] = sK[t][ii0 + i];
#pragma unroll
        for (int j = 0; j < 4; j++) vr[j] = sV[t][jj0 + j];
#pragma unroll
        for (int i = 0; i < 4; i++)
#pragma unroll
            for (int j = 0; j < 4; j++)
                a[i][j] += kr[i] * vr[j];
    }

    float* kvout = g_kv + (size_t)(bh * NCH + c) * (DD * DD);
#pragma unroll
    for (int i = 0; i < 4; i++)
        *(float4*)&kvout[(ii0 + i) * 64 + jj0] =
            make_float4(a[i][0], a[i][1], a[i][2], a[i][3]);

    if (tid < 64) {
        float s = 0.f;
#pragma unroll 8
        for (int t = 0; t < 64; t++) s += sK[t][tid];
        g_kz[(size_t)(bh * NCH + c) * 64 + tid] = s;
    }
}

// ---------------- Phase B: exclusive prefix over chunks (kv + kz merged) ------
__global__ void scan_all_kernel() {
    int e = blockIdx.x * 256 + threadIdx.x;
    if (e < BHN * 4096) {
        int bh = e >> 12, ij = e & 4095;
        float* p = g_kv + (size_t)bh * NCH * 4096 + ij;
        float run = 0.f;
#pragma unroll 4
        for (int c = 0; c < NCH; c++) {
            float v = p[(size_t)c * 4096];
            p[(size_t)c * 4096] = run;
            run += v;
        }
    } else if (e < BHN * 4096 + BHN * 64) {
        int e2 = e - BHN * 4096;
        int bh = e2 >> 6, i = e2 & 63;
        float* p = g_kz + (size_t)bh * NCH * 64 + i;
        float run = 0.f;
#pragma unroll 4
        for (int c = 0; c < NCH; c++) {
            float v = p[(size_t)c * 64];
            p[(size_t)c * 64] = run;
            run += v;
        }
    }
}

// ---------------- Phase C: tensor-core per-chunk output ------------------------
// P = mask(Q K^T); Y' = Q @ S' + P @ V'  where S' col64 = z, V' col64 = ones.
// den = Y'[:,64]; y = Y'[:,0:64] / (den + eps).
// 128 threads = 4 warps, each warp owns 16 output rows end-to-end.
// Smem strides: A-operands (Q,P) 68 -> frag bank = lane; B-operands (Kt,S,V) 72.
#define ATTN_SMEM_WORDS (64*68*2 + 64*72*3 + 64)
#define ATTN_SMEM_BYTES (ATTN_SMEM_WORDS * 4)

__global__ __launch_bounds__(128) void attn_out_tc_kernel() {
    extern __shared__ uint32_t sm[];
    uint32_t* sQ  = sm;              // [64][68]  phi(Q), tf32
    uint32_t* sP  = sm + 64 * 68;    // [64][68]  masked QK^T, tf32
    uint32_t* sKt = sm + 64 * 68 * 2;            // [64][72]  B: [d][s] = phi(K[s][d])
    uint32_t* sS  = sm + 64 * 68 * 2 + 64 * 72;  // [64][72]  S'
    uint32_t* sV  = sm + 64 * 68 * 2 + 64 * 72 * 2; // [64][72] V'
    float* sDen = (float*)(sm + 64 * 68 * 2 + 64 * 72 * 3);   // [64]

    int bid = blockIdx.x;
    int bh = bid >> 5, cidx = bid & 31;
    int b = bh >> 4, h = bh & 15;
    int tid = threadIdx.x;
    int lane = tid & 31;
    int warp = tid >> 5;
    int wrow = warp * 16;
    int lq = lane >> 2, lr = lane & 3;

    const float* base = g_qkv + (size_t)(b * TB + cidx * 64) * (3 * CB) + h * 64;
    const float* Sg = g_kv + (size_t)(bh * NCH + cidx) * 4096;

#pragma unroll
    for (int it = 0; it < 8; it++) {
        int idx = it * 128 + tid;                 // 0..1023
        int r = idx >> 4, c4 = (idx & 15) << 2;
        float4 q4 = *(const float4*)(base + (size_t)r * (3 * CB) + c4);
        float4 v4 = *(const float4*)(base + (size_t)r * (3 * CB) + 2 * CB + c4);
        float4 s4 = *(const float4*)(Sg + r * 64 + c4);
        sQ[r * 68 + c4 + 0] = f2tf32(phi(q4.x));
        sQ[r * 68 + c4 + 1] = f2tf32(phi(q4.y));
        sQ[r * 68 + c4 + 2] = f2tf32(phi(q4.z));
        sQ[r * 68 + c4 + 3] = f2tf32(phi(q4.w));
        sV[r * 72 + c4 + 0] = f2tf32(v4.x);
        sV[r * 72 + c4 + 1] = f2tf32(v4.y);
        sV[r * 72 + c4 + 2] = f2tf32(v4.z);
        sV[r * 72 + c4 + 3] = f2tf32(v4.w);
        sS[r * 72 + c4 + 0] = f2tf32(s4.x);
        sS[r * 72 + c4 + 1] = f2tf32(s4.y);
        sS[r * 72 + c4 + 2] = f2tf32(s4.z);
        sS[r * 72 + c4 + 3] = f2tf32(s4.w);
        int tt = idx & 63, kc = (idx >> 6) << 2;  // transpose K
        float4 k4 = *(const float4*)(base + (size_t)tt * (3 * CB) + CB + kc);
        sKt[(kc + 0) * 72 + tt] = f2tf32(phi(k4.x));
        sKt[(kc + 1) * 72 + tt] = f2tf32(phi(k4.y));
        sKt[(kc + 2) * 72 + tt] = f2tf32(phi(k4.z));
        sKt[(kc + 3) * 72 + tt] = f2tf32(phi(k4.w));
    }
    if (tid < 64) {
        sV[tid * 72 + 64] = 0x3f800000u;          // ones column
        sS[tid * 72 + 64] = f2tf32(g_kz[(size_t)(bh * NCH + cidx) * 64 + tid]);
#pragma unroll
        for (int j = 65; j < 72; j++) { sV[tid * 72 + j] = 0u; sS[tid * 72 + j] = 0u; }
    }
    __syncthreads();

    int r0 = wrow + lq, r1 = r0 + 8;

    // ---- Phase 1: P = mask(Q K^T) ----
    float pc[8][4];
#pragma unroll
    for (int nt = 0; nt < 8; nt++)
#pragma unroll
        for (int r = 0; r < 4; r++) pc[nt][r] = 0.f;

#pragma unroll
    for (int ks = 0; ks < 8; ks++) {
        int kb = ks * 8;
        uint32_t a0 = sQ[r0 * 68 + kb + lr];
        uint32_t a1 = sQ[r1 * 68 + kb + lr];
        uint32_t a2 = sQ[r0 * 68 + kb + 4 + lr];
        uint32_t a3 = sQ[r1 * 68 + kb + 4 + lr];
#pragma unroll
        for (int nt = 0; nt < 8; nt++) {
            uint32_t b0 = sKt[(kb + lr) * 72 + nt * 8 + lq];
            uint32_t b1 = sKt[(kb + 4 + lr) * 72 + nt * 8 + lq];
            MMA_TF32(pc[nt], a0, a1, a2, a3, b0, b1);
        }
    }
#pragma unroll
    for (int nt = 0; nt < 8; nt++) {
        int s0 = nt * 8 + 2 * lr;
        sP[r0 * 68 + s0    ] = f2tf32((s0     <= r0) ? pc[nt][0] : 0.f);
        sP[r0 * 68 + s0 + 1] = f2tf32((s0 + 1 <= r0) ? pc[nt][1] : 0.f);
        sP[r1 * 68 + s0    ] = f2tf32((s0     <= r1) ? pc[nt][2] : 0.f);
        sP[r1 * 68 + s0 + 1] = f2tf32((s0 + 1 <= r1) ? pc[nt][3] : 0.f);
    }
    __syncwarp();   // P rows are warp-local: producer == consumer warp

    // ---- Phase 2: Y' = Q @ S' + P @ V' ----
    float acc[9][4];
#pragma unroll
    for (int nt = 0; nt < 9; nt++)
#pragma unroll
        for (int r = 0; r < 4; r++) acc[nt][r] = 0.f;

#pragma unroll
    for (int ks = 0; ks < 8; ks++) {
        int kb = ks * 8;
        uint32_t q0 = sQ[r0 * 68 + kb + lr];
        uint32_t q1 = sQ[r1 * 68 + kb + lr];
        uint32_t q2 = sQ[r0 * 68 + kb + 4 + lr];
        uint32_t q3 = sQ[r1 * 68 + kb + 4 + lr];
        uint32_t p0 = sP[r0 * 68 + kb + lr];
        uint32_t p1 = sP[r1 * 68 + kb + lr];
        uint32_t p2 = sP[r0 * 68 + kb + 4 + lr];
        uint32_t p3 = sP[r1 * 68 + kb + 4 + lr];
#pragma unroll
        for (int nt = 0; nt < 9; nt++) {
            int n0 = nt * 8;
            uint32_t bs0 = sS[(kb + lr) * 72 + n0 + lq];
            uint32_t bs1 = sS[(kb + 4 + lr) * 72 + n0 + lq];
            MMA_TF32(acc[nt], q0, q1, q2, q3, bs0, bs1);
            uint32_t bv0 = sV[(kb + lr) * 72 + n0 + lq];
            uint32_t bv1 = sV[(kb + 4 + lr) * 72 + n0 + lq];
            MMA_TF32(acc[nt], p0, p1, p2, p3, bv0, bv1);
        }
    }

    if (lr == 0) { sDen[r0] = acc[8][0]; sDen[r1] = acc[8][2]; }
    __syncwarp();
    float inv0 = 1.f / (sDen[r0] + 1e-6f);
    float inv1 = 1.f / (sDen[r1] + 1e-6f);

    float* yb = g_y + (size_t)(b * TB + cidx * 64) * CB + h * 64;
#pragma unroll
    for (int nt = 0; nt < 8; nt++) {
        int col = nt * 8 + 2 * lr;
        *(float2*)(yb + (size_t)r0 * CB + col) =
            make_float2(acc[nt][0] * inv0, acc[nt][1] * inv0);
        *(float2*)(yb + (size_t)r1 * CB + col) =
            make_float2(acc[nt][2] * inv1, acc[nt][3] * inv1);
    }
}

// ---------------- launch ------------------------------------------------------
extern "C" void kernel_launch(void* const* d_in, const int* in_sizes, int n_in,
                              void* d_out, int out_size) {
    const float* x      = (const float*)d_in[0];
    const float* w_attn = (const float*)d_in[1];
    const float* w_proj = (const float*)d_in[2];
    float* out = (float*)d_out;

    cudaFuncSetAttribute(attn_out_tc_kernel,
                         cudaFuncAttributeMaxDynamicSharedMemorySize, ATTN_SMEM_BYTES);

    dim3 g1(3 * CB / 128, BSZ * TB / 128);   // (24, 32)
    gemm_qkv_kernel<<<g1, 256>>>(x, w_attn);

    chunk_kv_kernel<<<BHN * NCH, 256>>>();
    scan_all_kernel<<<(BHN * 4096 + BHN * 64 + 255) / 256, 256>>>();
    attn_out_tc_kernel<<<BHN * NCH, 128, ATTN_SMEM_BYTES>>>();

    dim3 g2(CB / 128, BSZ * TB / 128);       // (8, 32)
    gemm_proj_kernel<<<g2, 256>>>(w_proj, out);
}